// round 4
// baseline (speedup 1.0000x reference)
#include <cuda_runtime.h>
#include <cstdint>

// VisibilityHeatmap: out[b,k] = in_bounds(coords[b,k]) && heatmaps[b,k,v,u] > 0.4
// coords: [B,K,2] int32 in (u,v) order; heatmaps: [B,K,H,W] f32.
// Output: [B,K] boolean mask materialized as float32 (0.0f / 1.0f).
#define B_DIM 128
#define K_DIM 64
#define H_DIM 128
#define W_DIM 128
#define THRESH 0.4f

// 64 threads/block, 128 blocks -> one thin wave covering ~128 of 148 SMs.
// Spreads the 8192 scattered gathers across maximal LSU/L1tex/TLB paths.
__global__ __launch_bounds__(64)
void visibility_kernel(const int2* __restrict__ coords,
                       const float* __restrict__ heatmaps,
                       float* __restrict__ out)
{
    int idx = blockIdx.x * 64 + threadIdx.x;   // idx = b*K + k, 0..8191

    int2 c = coords[idx];           // c.x = u (W index), c.y = v (H index)
    int u = c.x;
    int v = c.y;

    bool in_bounds = (v > -1) & (u > -1) & (v < H_DIM) & (u < W_DIM);

    int vc = min(max(v, 0), H_DIM - 1);
    int uc = min(max(u, 0), W_DIM - 1);

    // heatmaps[idx, vc, uc] — per-(b,k) plane of H*W floats
    float val = __ldg(&heatmaps[(size_t)idx * (H_DIM * W_DIM) + vc * W_DIM + uc]);

    out[idx] = (in_bounds && (val > THRESH)) ? 1.0f : 0.0f;
}

extern "C" void kernel_launch(void* const* d_in, const int* in_sizes, int n_in,
                              void* d_out, int out_size)
{
    const int2*  coords   = (const int2*)d_in[0];    // [B,K,2] int32
    const float* heatmaps = (const float*)d_in[1];   // [B,K,H,W] f32
    float*       out      = (float*)d_out;           // [B,K] mask as f32

    visibility_kernel<<<128, 64>>>(coords, heatmaps, out);
}

// round 5
// speedup vs baseline: 1.0386x; 1.0386x over previous
#include <cuda_runtime.h>
#include <cstdint>

// VisibilityHeatmap: out[b,k] = in_bounds(coords[b,k]) && heatmaps[b,k,v,u] > 0.4
// coords: [B,K,2] int32 in (u,v) order; heatmaps: [B,K,H,W] f32.
// Output: [B,K] boolean mask materialized as float32 (0.0f / 1.0f).
//
// 4 outputs per thread: 2048 threads = 16 blocks x 128. Coord loads as 2x int4
// (coalesced), 4 independent gathers (MLP=4, front-batched by ptxas), 1 float4
// store. Minimizes warp count / block-distribution overhead, which R3 showed
// dominates over per-SM queueing for this size.
#define B_DIM 128
#define K_DIM 64
#define H_DIM 128
#define W_DIM 128
#define N_TOTAL (B_DIM * K_DIM)   // 8192
#define THRESH 0.4f

__global__ __launch_bounds__(128)
void visibility_kernel(const int4* __restrict__ coords4,   // pairs of (u,v),(u,v)
                       const float* __restrict__ heatmaps,
                       float4* __restrict__ out4)
{
    int t = blockIdx.x * 128 + threadIdx.x;    // 0..2047, handles outputs [4t, 4t+4)

    // 4 coords = 8 ints = 2 x int4
    int4 c01 = coords4[2 * t];
    int4 c23 = coords4[2 * t + 1];

    int u0 = c01.x, v0 = c01.y;
    int u1 = c01.z, v1 = c01.w;
    int u2 = c23.x, v2 = c23.y;
    int u3 = c23.z, v3 = c23.w;

    bool ib0 = (v0 > -1) & (u0 > -1) & (v0 < H_DIM) & (u0 < W_DIM);
    bool ib1 = (v1 > -1) & (u1 > -1) & (v1 < H_DIM) & (u1 < W_DIM);
    bool ib2 = (v2 > -1) & (u2 > -1) & (v2 < H_DIM) & (u2 < W_DIM);
    bool ib3 = (v3 > -1) & (u3 > -1) & (v3 < H_DIM) & (u3 < W_DIM);

    size_t base = (size_t)(4 * t) * (H_DIM * W_DIM);
    const float* p = heatmaps + base;

    // 4 independent gathers — issue back-to-back, latency overlapped.
    float f0 = __ldg(p + 0 * (H_DIM * W_DIM)
                     + min(max(v0, 0), H_DIM - 1) * W_DIM + min(max(u0, 0), W_DIM - 1));
    float f1 = __ldg(p + 1 * (H_DIM * W_DIM)
                     + min(max(v1, 0), H_DIM - 1) * W_DIM + min(max(u1, 0), W_DIM - 1));
    float f2 = __ldg(p + 2 * (H_DIM * W_DIM)
                     + min(max(v2, 0), H_DIM - 1) * W_DIM + min(max(u2, 0), W_DIM - 1));
    float f3 = __ldg(p + 3 * (H_DIM * W_DIM)
                     + min(max(v3, 0), H_DIM - 1) * W_DIM + min(max(u3, 0), W_DIM - 1));

    float4 r;
    r.x = (ib0 && (f0 > THRESH)) ? 1.0f : 0.0f;
    r.y = (ib1 && (f1 > THRESH)) ? 1.0f : 0.0f;
    r.z = (ib2 && (f2 > THRESH)) ? 1.0f : 0.0f;
    r.w = (ib3 && (f3 > THRESH)) ? 1.0f : 0.0f;
    out4[t] = r;
}

extern "C" void kernel_launch(void* const* d_in, const int* in_sizes, int n_in,
                              void* d_out, int out_size)
{
    const int4*  coords4  = (const int4*)d_in[0];    // [B,K,2] int32, viewed as int4
    const float* heatmaps = (const float*)d_in[1];   // [B,K,H,W] f32
    float4*      out4     = (float4*)d_out;          // [B,K] mask as f32, viewed as float4

    // 8192 outputs / 4 per thread = 2048 threads = 16 blocks x 128
    visibility_kernel<<<16, 128>>>(coords4, heatmaps, out4);
}